// round 5
// baseline (speedup 1.0000x reference)
#include <cuda_runtime.h>
#include <math.h>

#define NROWS 32768
#define NCODE 8192
#define DIM   512

#define BM 64
#define BN 64
#define BK 16

// scratch (no allocations allowed)
__device__ float g_x2[NROWS];
__device__ float g_y2[NCODE];
__device__ unsigned long long g_best[NROWS];

__device__ __forceinline__ unsigned int fkey(float v) {
    // order-preserving map float -> uint (ascending)
    unsigned int b = __float_as_uint(v);
    return (b & 0x80000000u) ? ~b : (b | 0x80000000u);
}

__global__ void init_best() {
    int i = blockIdx.x * blockDim.x + threadIdx.x;
    if (i < NROWS) g_best[i] = 0ull;
}

// Bit-replication of XLA-CPU's reduce: strictly SEQUENTIAL scalar fp32,
// ascending element order, separate mul and add roundings (no FMA contraction).
// One thread per row; float4 loads preserve order within each quad.
__global__ __launch_bounds__(128)
void row_norms_seq(const float* __restrict__ m, float* __restrict__ out, int rows) {
    int row = blockIdx.x * blockDim.x + threadIdx.x;
    if (row >= rows) return;
    const float4* p = reinterpret_cast<const float4*>(m + (size_t)row * DIM);
    float s = 0.0f;
    #pragma unroll 4
    for (int j = 0; j < DIM / 4; j++) {
        float4 v = p[j];
        s = __fadd_rn(s, __fmul_rn(v.x, v.x));
        s = __fadd_rn(s, __fmul_rn(v.y, v.y));
        s = __fadd_rn(s, __fmul_rn(v.z, v.z));
        s = __fadd_rn(s, __fmul_rn(v.w, v.w));
    }
    out[row] = s;
}

// xy accumulation: strictly ascending-k fp32 FMA chain per output element,
// matching Eigen's gebp micro-kernel (single accumulator per output, MADD).
__global__ __launch_bounds__(256)
void gemm_dist(const float* __restrict__ x, const float* __restrict__ e,
               float* __restrict__ dist) {
    __shared__ float xs[BK][BM + 1];
    __shared__ float es[BK][BN + 1];

    int tid = threadIdx.x;
    int tx = tid & 15;
    int ty = tid >> 4;
    int bm = blockIdx.y * BM;
    int bn = blockIdx.x * BN;

    int lrow = tid >> 2;
    int lk   = (tid & 3) * 4;

    const float* xptr = x + (size_t)(bm + lrow) * DIM + lk;
    const float* eptr = e + (size_t)(bn + lrow) * DIM + lk;

    float acc[4][4] = {};

    for (int k0 = 0; k0 < DIM; k0 += BK) {
        float4 xa = *reinterpret_cast<const float4*>(xptr + k0);
        float4 ea = *reinterpret_cast<const float4*>(eptr + k0);
        xs[lk + 0][lrow] = xa.x; xs[lk + 1][lrow] = xa.y;
        xs[lk + 2][lrow] = xa.z; xs[lk + 3][lrow] = xa.w;
        es[lk + 0][lrow] = ea.x; es[lk + 1][lrow] = ea.y;
        es[lk + 2][lrow] = ea.z; es[lk + 3][lrow] = ea.w;
        __syncthreads();

        #pragma unroll
        for (int k = 0; k < BK; k++) {     // strictly ascending k
            float a[4], b[4];
            #pragma unroll
            for (int i = 0; i < 4; i++) a[i] = xs[k][ty + 16 * i];
            #pragma unroll
            for (int j = 0; j < 4; j++) b[j] = es[k][tx + 16 * j];
            #pragma unroll
            for (int i = 0; i < 4; i++)
                #pragma unroll
                for (int j = 0; j < 4; j++)
                    acc[i][j] = fmaf(a[i], b[j], acc[i][j]);
        }
        __syncthreads();
    }

    // epilogue with the reference's rounding structure:
    //   t = fl(x2 + y2); dsq = fl(t + fl(-2*xy)); d = -sqrtf(max(dsq,0))
    float x2r[4], y2c[4];
    #pragma unroll
    for (int i = 0; i < 4; i++) x2r[i] = g_x2[bm + ty + 16 * i];
    #pragma unroll
    for (int j = 0; j < 4; j++) y2c[j] = g_y2[bn + tx + 16 * j];

    #pragma unroll
    for (int i = 0; i < 4; i++) {
        int r = bm + ty + 16 * i;
        unsigned long long best = 0ull;
        #pragma unroll
        for (int j = 0; j < 4; j++) {
            int c = bn + tx + 16 * j;
            float xyv = __fmul_rn(-2.0f, acc[i][j]);
            float t   = __fadd_rn(x2r[i], y2c[j]);
            float dsq = __fadd_rn(t, xyv);
            float dv  = -sqrtf(fmaxf(dsq, 0.0f));
            dist[(size_t)r * NCODE + c] = dv;
            unsigned long long p =
                ((unsigned long long)fkey(dv) << 32) |
                (unsigned int)(NCODE - 1 - c);   // exact fp32 tie -> lowest index
            best = (p > best) ? p : best;
        }
        #pragma unroll
        for (int off = 8; off > 0; off >>= 1) {
            unsigned long long o = __shfl_down_sync(0xffffffffu, best, off, 16);
            best = (o > best) ? o : best;
        }
        if (tx == 0) atomicMax(&g_best[r], best);
    }
}

__global__ void finalize(const float* __restrict__ embed,
                         float* __restrict__ out_q,
                         float* __restrict__ out_ind) {
    int row = blockIdx.x;
    unsigned long long p = g_best[row];
    int c = (NCODE - 1) - (int)(unsigned int)(p & 0xFFFFFFFFull);
    if (threadIdx.x == 0) out_ind[row] = (float)c;
    const float4* src = reinterpret_cast<const float4*>(embed + (size_t)c * DIM);
    float4* dst = reinterpret_cast<float4*>(out_q + (size_t)row * DIM);
    for (int j = threadIdx.x; j < DIM / 4; j += blockDim.x) dst[j] = src[j];
}

extern "C" void kernel_launch(void* const* d_in, const int* in_sizes, int n_in,
                              void* d_out, int out_size) {
    const float* x = (const float*)d_in[0];      // [32768, 512]
    const float* e = (const float*)d_in[1];      // [8192, 512]
    float* out = (float*)d_out;

    float* out_q    = out;                                   // [N, D]
    float* out_ind  = out + (size_t)NROWS * DIM;             // [N]
    float* out_dist = out + (size_t)NROWS * DIM + NROWS;     // [N, C]

    init_best<<<(NROWS + 255) / 256, 256>>>();

    float* d_x2; float* d_y2;
    cudaGetSymbolAddress((void**)&d_x2, g_x2);
    cudaGetSymbolAddress((void**)&d_y2, g_y2);

    row_norms_seq<<<NROWS / 128, 128>>>(x, d_x2, NROWS);
    row_norms_seq<<<NCODE / 128, 128>>>(e, d_y2, NCODE);

    dim3 grid(NCODE / BN, NROWS / BM);
    gemm_dist<<<grid, 256>>>(x, e, out_dist);

    finalize<<<NROWS, 128>>>(e, out_q, out_ind);
}

// round 6
// speedup vs baseline: 4.7735x; 4.7735x over previous
#include <cuda_runtime.h>
#include <cuda_bf16.h>
#include <math.h>

#define NROWS 32768
#define NCODE 8192
#define DIM   512

#define BM 128
#define BN 64
#define KS 32
#define LDA 40          // KS + 8 pad (bf16 elems) -> conflict-free ldmatrix

#define MARGIN 0.02f
#define MAXCAND 32

// scratch (no allocations allowed)
__device__ float g_x2[NROWS];
__device__ float g_y2[NCODE];
__device__ unsigned int g_rowmax[NROWS];
__device__ int g_bestidx[NROWS];
__device__ __nv_bfloat16 g_xb[NROWS * DIM];
__device__ __nv_bfloat16 g_eb[NCODE * DIM];

__device__ __forceinline__ unsigned int fkey(float v) {
    unsigned int b = __float_as_uint(v);
    return (b & 0x80000000u) ? ~b : (b | 0x80000000u);
}
__device__ __forceinline__ float fkey_inv(unsigned int k) {
    unsigned int b = (k & 0x80000000u) ? (k & 0x7FFFFFFFu) : ~k;
    return __uint_as_float(b);
}

__global__ void init_scratch() {
    int i = blockIdx.x * blockDim.x + threadIdx.x;
    if (i < NROWS) g_rowmax[i] = 0u;
}

__global__ void convert_bf16(const float* __restrict__ s, __nv_bfloat16* __restrict__ d, int n4) {
    int i = blockIdx.x * blockDim.x + threadIdx.x;
    if (i < n4) {
        float4 v = reinterpret_cast<const float4*>(s)[i];
        __nv_bfloat162 lo = __floats2bfloat162_rn(v.x, v.y);
        __nv_bfloat162 hi = __floats2bfloat162_rn(v.z, v.w);
        reinterpret_cast<__nv_bfloat162*>(d)[2 * i]     = lo;
        reinterpret_cast<__nv_bfloat162*>(d)[2 * i + 1] = hi;
    }
}

// strictly sequential scalar fp32 (bit-matches XLA-CPU reduce) — VALIDATED R5
__global__ __launch_bounds__(128)
void row_norms_seq(const float* __restrict__ m, float* __restrict__ out, int rows) {
    int row = blockIdx.x * blockDim.x + threadIdx.x;
    if (row >= rows) return;
    const float4* p = reinterpret_cast<const float4*>(m + (size_t)row * DIM);
    float s = 0.0f;
    #pragma unroll 4
    for (int j = 0; j < DIM / 4; j++) {
        float4 v = p[j];
        s = __fadd_rn(s, __fmul_rn(v.x, v.x));
        s = __fadd_rn(s, __fmul_rn(v.y, v.y));
        s = __fadd_rn(s, __fmul_rn(v.z, v.z));
        s = __fadd_rn(s, __fmul_rn(v.w, v.w));
    }
    out[row] = s;
}

__device__ __forceinline__ void ldsm_x4(unsigned& r0, unsigned& r1, unsigned& r2, unsigned& r3,
                                        const void* ptr) {
    unsigned addr = (unsigned)__cvta_generic_to_shared(ptr);
    asm volatile("ldmatrix.sync.aligned.m8n8.x4.shared.b16 {%0,%1,%2,%3}, [%4];"
                 : "=r"(r0), "=r"(r1), "=r"(r2), "=r"(r3) : "r"(addr));
}
__device__ __forceinline__ void mma_bf16(float* c, const unsigned* a, const unsigned* b) {
    asm volatile(
        "mma.sync.aligned.m16n8k16.row.col.f32.bf16.bf16.f32 "
        "{%0,%1,%2,%3}, {%4,%5,%6,%7}, {%8,%9}, {%0,%1,%2,%3};"
        : "+f"(c[0]), "+f"(c[1]), "+f"(c[2]), "+f"(c[3])
        : "r"(a[0]), "r"(a[1]), "r"(a[2]), "r"(a[3]), "r"(b[0]), "r"(b[1]));
}

// bf16 tensor-core GEMM: dist (approx, well within 1e-3) + per-row approx max
__global__ __launch_bounds__(256)
void gemm_bf16(float* __restrict__ dist) {
    __shared__ __nv_bfloat16 As[2][BM][LDA];
    __shared__ __nv_bfloat16 Bs[2][BN][LDA];

    int tid = threadIdx.x;
    int wid = tid >> 5, lane = tid & 31;
    int warp_m = wid >> 1, warp_n = wid & 1;          // 4 x 2 warps, warp tile 32x32
    int bm = blockIdx.y * BM, bn = blockIdx.x * BN;

    // loaders
    int a_row = tid >> 1, a_seg = (tid & 1) * 2;      // 2 x uint4 per thread (A)
    int b_row = tid >> 2, b_seg = tid & 3;            // 1 x uint4 per thread (B)
    const uint4* agp = reinterpret_cast<const uint4*>(g_xb + (size_t)(bm + a_row) * DIM) + a_seg;
    const uint4* bgp = reinterpret_cast<const uint4*>(g_eb + (size_t)(bn + b_row) * DIM) + b_seg;

    float acc[2][4][4] = {};

    uint4 pa0 = agp[0], pa1 = agp[1], pb = bgp[0];

    #pragma unroll 1
    for (int kt = 0; kt < DIM / KS; kt++) {
        int buf = kt & 1;
        // store prefetched tile
        *reinterpret_cast<uint4*>(&As[buf][a_row][a_seg * 8])       = pa0;
        *reinterpret_cast<uint4*>(&As[buf][a_row][(a_seg + 1) * 8]) = pa1;
        *reinterpret_cast<uint4*>(&Bs[buf][b_row][b_seg * 8])       = pb;
        __syncthreads();
        if (kt + 1 < DIM / KS) {
            pa0 = agp[(kt + 1) * 4];
            pa1 = agp[(kt + 1) * 4 + 1];
            pb  = bgp[(kt + 1) * 4];
        }

        #pragma unroll
        for (int kk = 0; kk < 2; kk++) {
            unsigned a[2][4], b[4][2];
            #pragma unroll
            for (int mi = 0; mi < 2; mi++)
                ldsm_x4(a[mi][0], a[mi][1], a[mi][2], a[mi][3],
                        &As[buf][warp_m * 32 + mi * 16 + (lane & 15)][kk * 16 + ((lane >> 4) << 3)]);
            #pragma unroll
            for (int nib = 0; nib < 2; nib++) {
                unsigned r0, r1, r2, r3;
                ldsm_x4(r0, r1, r2, r3,
                        &Bs[buf][warp_n * 32 + nib * 16 + ((lane >> 4) << 3) + (lane & 7)]
                           [kk * 16 + ((lane >> 3) & 1) * 8]);
                b[nib * 2][0] = r0; b[nib * 2][1] = r1;
                b[nib * 2 + 1][0] = r2; b[nib * 2 + 1][1] = r3;
            }
            #pragma unroll
            for (int mi = 0; mi < 2; mi++)
                #pragma unroll
                for (int ni = 0; ni < 4; ni++)
                    mma_bf16(acc[mi][ni], a[mi], b[ni]);
        }
        __syncthreads();
    }

    // epilogue: dv = -sqrt(max((x2+y2) + (-2*xy), 0)); approx row max
    int qr = lane >> 2, qc = 2 * (lane & 3);
    float x2v[2][2], rmax[2][2];
    #pragma unroll
    for (int mi = 0; mi < 2; mi++)
        #pragma unroll
        for (int h = 0; h < 2; h++) {
            x2v[mi][h] = g_x2[bm + warp_m * 32 + mi * 16 + h * 8 + qr];
            rmax[mi][h] = -1e30f;
        }

    #pragma unroll
    for (int ni = 0; ni < 4; ni++) {
        int n0 = bn + warp_n * 32 + ni * 8 + qc;
        float y0 = g_y2[n0], y1 = g_y2[n0 + 1];
        #pragma unroll
        for (int mi = 0; mi < 2; mi++)
            #pragma unroll
            for (int h = 0; h < 2; h++) {
                int rg = bm + warp_m * 32 + mi * 16 + h * 8 + qr;
                float s0 = acc[mi][ni][2 * h], s1 = acc[mi][ni][2 * h + 1];
                float d0 = -sqrtf(fmaxf(__fadd_rn(__fadd_rn(x2v[mi][h], y0), __fmul_rn(-2.0f, s0)), 0.0f));
                float d1 = -sqrtf(fmaxf(__fadd_rn(__fadd_rn(x2v[mi][h], y1), __fmul_rn(-2.0f, s1)), 0.0f));
                *reinterpret_cast<float2*>(&dist[(size_t)rg * NCODE + n0]) = make_float2(d0, d1);
                float mx = fmaxf(d0, d1);
                rmax[mi][h] = fmaxf(rmax[mi][h], mx);
            }
    }
    #pragma unroll
    for (int mi = 0; mi < 2; mi++)
        #pragma unroll
        for (int h = 0; h < 2; h++) {
            float v = rmax[mi][h];
            v = fmaxf(v, __shfl_xor_sync(0xffffffffu, v, 1));
            v = fmaxf(v, __shfl_xor_sync(0xffffffffu, v, 2));
            if ((lane & 3) == 0)
                atomicMax(&g_rowmax[bm + warp_m * 32 + mi * 16 + h * 8 + qr], fkey(v));
        }
}

// one warp per row: candidates within MARGIN of approx max, re-evaluated with the
// EXACT validated R5 chain (sequential ascending-k fmaf + exact epilogue roundings),
// argmax with exact-fp32-tie -> lowest index.
#define RWARPS 8
__global__ __launch_bounds__(256)
void rescue(const float* __restrict__ x, const float* __restrict__ e,
            const float* __restrict__ dist) {
    __shared__ int s_cnt[RWARPS];
    __shared__ int s_cand[RWARPS][MAXCAND];

    int w = threadIdx.x >> 5, lane = threadIdx.x & 31;
    int row = blockIdx.x * RWARPS + w;

    if (lane == 0) s_cnt[w] = 0;
    __syncwarp();

    float thr = fkey_inv(g_rowmax[row]) - MARGIN;
    const float4* dp = reinterpret_cast<const float4*>(dist + (size_t)row * NCODE);
    for (int j = lane; j < NCODE / 4; j += 32) {
        float4 v = dp[j];
        #pragma unroll
        for (int q = 0; q < 4; q++) {
            float dv = (q == 0) ? v.x : (q == 1) ? v.y : (q == 2) ? v.z : v.w;
            if (dv >= thr) {
                int slot = atomicAdd(&s_cnt[w], 1);
                if (slot < MAXCAND) s_cand[w][slot] = 4 * j + q;
            }
        }
    }
    __syncwarp();
    int cnt = s_cnt[w];
    if (cnt > MAXCAND) cnt = MAXCAND;

    unsigned long long key = 0ull;
    if (lane < cnt) {
        int c = s_cand[w][lane];
        const float* xr = x + (size_t)row * DIM;
        const float* er = e + (size_t)c * DIM;
        float s = 0.0f;
        #pragma unroll 8
        for (int k = 0; k < DIM; k++)          // strictly ascending-k fp32 FMA chain
            s = fmaf(xr[k], er[k], s);
        float xyv = __fmul_rn(-2.0f, s);
        float t   = __fadd_rn(g_x2[row], g_y2[c]);
        float dsq = __fadd_rn(t, xyv);
        float dv  = -sqrtf(fmaxf(dsq, 0.0f));
        key = ((unsigned long long)fkey(dv) << 32) | (unsigned int)(NCODE - 1 - c);
    }
    #pragma unroll
    for (int off = 16; off > 0; off >>= 1) {
        unsigned long long o = __shfl_xor_sync(0xffffffffu, key, off);
        key = (o > key) ? o : key;
    }
    if (lane == 0)
        g_bestidx[row] = (NCODE - 1) - (int)(unsigned int)(key & 0xFFFFFFFFull);
}

__global__ void finalize(const float* __restrict__ embed,
                         float* __restrict__ out_q,
                         float* __restrict__ out_ind) {
    int row = blockIdx.x;
    int c = g_bestidx[row];
    if (threadIdx.x == 0) out_ind[row] = (float)c;
    const float4* src = reinterpret_cast<const float4*>(embed + (size_t)c * DIM);
    float4* dst = reinterpret_cast<float4*>(out_q + (size_t)row * DIM);
    for (int j = threadIdx.x; j < DIM / 4; j += blockDim.x) dst[j] = src[j];
}

extern "C" void kernel_launch(void* const* d_in, const int* in_sizes, int n_in,
                              void* d_out, int out_size) {
    const float* x = (const float*)d_in[0];      // [32768, 512]
    const float* e = (const float*)d_in[1];      // [8192, 512]
    float* out = (float*)d_out;

    float* out_q    = out;                                   // [N, D]
    float* out_ind  = out + (size_t)NROWS * DIM;             // [N]
    float* out_dist = out + (size_t)NROWS * DIM + NROWS;     // [N, C]

    float *d_x2, *d_y2;
    __nv_bfloat16 *d_xb, *d_eb;
    cudaGetSymbolAddress((void**)&d_x2, g_x2);
    cudaGetSymbolAddress((void**)&d_y2, g_y2);
    cudaGetSymbolAddress((void**)&d_xb, g_xb);
    cudaGetSymbolAddress((void**)&d_eb, g_eb);

    init_scratch<<<(NROWS + 255) / 256, 256>>>();
    convert_bf16<<<(NROWS * DIM / 4 + 255) / 256, 256>>>(x, d_xb, NROWS * DIM / 4);
    convert_bf16<<<(NCODE * DIM / 4 + 255) / 256, 256>>>(e, d_eb, NCODE * DIM / 4);
    row_norms_seq<<<NROWS / 128, 128>>>(x, d_x2, NROWS);
    row_norms_seq<<<NCODE / 128, 128>>>(e, d_y2, NCODE);

    dim3 grid(NCODE / BN, NROWS / BM);
    gemm_bf16<<<grid, 256>>>(out_dist);

    rescue<<<NROWS / RWARPS, 256>>>(x, e, out_dist);

    finalize<<<NROWS, 128>>>(e, out_q, out_ind);
}

// round 7
// speedup vs baseline: 6.8141x; 1.4275x over previous
#include <cuda_runtime.h>
#include <cuda_bf16.h>
#include <math.h>

#define NROWS 32768
#define NCODE 8192
#define DIM   512

#define BM 128
#define BN 128
#define KS 32
#define KT (DIM / KS)
#define NSTAGE 3
#define LDA 40          // KS + 8 pad (bf16) -> conflict-free ldmatrix, 16B-aligned rows

#define MARGIN 0.02f
#define MAXCAND 32

#define SMEM_BYTES (NSTAGE * (BM + BN) * LDA * 2)

// scratch (no allocations allowed)
__device__ float g_x2[NROWS];
__device__ float g_y2[NCODE];
__device__ unsigned int g_rowmax[NROWS];
__device__ int g_bestidx[NROWS];
__device__ __nv_bfloat16 g_xb[NROWS * DIM];
__device__ __nv_bfloat16 g_eb[NCODE * DIM];

__device__ __forceinline__ unsigned int fkey(float v) {
    unsigned int b = __float_as_uint(v);
    return (b & 0x80000000u) ? ~b : (b | 0x80000000u);
}
__device__ __forceinline__ float fkey_inv(unsigned int k) {
    unsigned int b = (k & 0x80000000u) ? (k & 0x7FFFFFFFu) : ~k;
    return __uint_as_float(b);
}

__global__ void init_scratch() {
    int i = blockIdx.x * blockDim.x + threadIdx.x;
    if (i < NROWS) g_rowmax[i] = 0u;
}

__global__ void convert_bf16(const float* __restrict__ s, __nv_bfloat16* __restrict__ d, int n4) {
    int i = blockIdx.x * blockDim.x + threadIdx.x;
    if (i < n4) {
        float4 v = reinterpret_cast<const float4*>(s)[i];
        __nv_bfloat162 lo = __floats2bfloat162_rn(v.x, v.y);
        __nv_bfloat162 hi = __floats2bfloat162_rn(v.z, v.w);
        reinterpret_cast<__nv_bfloat162*>(d)[2 * i]     = lo;
        reinterpret_cast<__nv_bfloat162*>(d)[2 * i + 1] = hi;
    }
}

// strictly sequential scalar fp32 (bit-matches XLA-CPU reduce) — VALIDATED R5/R6
__global__ __launch_bounds__(128)
void row_norms_seq(const float* __restrict__ m, float* __restrict__ out, int rows) {
    int row = blockIdx.x * blockDim.x + threadIdx.x;
    if (row >= rows) return;
    const float4* p = reinterpret_cast<const float4*>(m + (size_t)row * DIM);
    float s = 0.0f;
    #pragma unroll 4
    for (int j = 0; j < DIM / 4; j++) {
        float4 v = p[j];
        s = __fadd_rn(s, __fmul_rn(v.x, v.x));
        s = __fadd_rn(s, __fmul_rn(v.y, v.y));
        s = __fadd_rn(s, __fmul_rn(v.z, v.z));
        s = __fadd_rn(s, __fmul_rn(v.w, v.w));
    }
    out[row] = s;
}

__device__ __forceinline__ void ldsm_x4(unsigned& r0, unsigned& r1, unsigned& r2, unsigned& r3,
                                        const void* ptr) {
    unsigned addr = (unsigned)__cvta_generic_to_shared(ptr);
    asm volatile("ldmatrix.sync.aligned.m8n8.x4.shared.b16 {%0,%1,%2,%3}, [%4];"
                 : "=r"(r0), "=r"(r1), "=r"(r2), "=r"(r3) : "r"(addr));
}
__device__ __forceinline__ void mma_bf16(float* c, const unsigned* a, const unsigned* b) {
    asm volatile(
        "mma.sync.aligned.m16n8k16.row.col.f32.bf16.bf16.f32 "
        "{%0,%1,%2,%3}, {%4,%5,%6,%7}, {%8,%9}, {%0,%1,%2,%3};"
        : "+f"(c[0]), "+f"(c[1]), "+f"(c[2]), "+f"(c[3])
        : "r"(a[0]), "r"(a[1]), "r"(a[2]), "r"(a[3]), "r"(b[0]), "r"(b[1]));
}
__device__ __forceinline__ void cp16(void* dst, const void* src) {
    unsigned d = (unsigned)__cvta_generic_to_shared(dst);
    asm volatile("cp.async.cg.shared.global [%0], [%1], 16;" :: "r"(d), "l"(src));
}
#define CP_COMMIT() asm volatile("cp.async.commit_group;")
#define CP_WAIT1()  asm volatile("cp.async.wait_group 1;")

// bf16 tensor-core GEMM, 3-stage cp.async pipeline, warp tile 64x32
__global__ __launch_bounds__(256)
void gemm_bf16(float* __restrict__ dist) {
    extern __shared__ __nv_bfloat16 smem[];
    __nv_bfloat16* As = smem;                            // [NSTAGE][BM][LDA]
    __nv_bfloat16* Bs = smem + NSTAGE * BM * LDA;        // [NSTAGE][BN][LDA]

    int tid = threadIdx.x;
    int wid = tid >> 5, lane = tid & 31;
    int warp_m = wid >> 2, warp_n = wid & 3;             // 2 x 4 warps, warp tile 64x32
    int bm = blockIdx.y * BM, bn = blockIdx.x * BN;

    // loaders: A/B tiles are 128 rows x 32 cols bf16 = 128 rows x 4 x 16B chunks
    int lr = tid >> 2;                // 0..63 (and +64)
    int ls = tid & 3;                 // 16B segment 0..3
    const __nv_bfloat16* xg = g_xb + (size_t)bm * DIM;
    const __nv_bfloat16* eg = g_eb + (size_t)bn * DIM;

    float acc[4][4][4] = {};

    auto issue = [&](int kt, int s) {
        const __nv_bfloat16* xsrc = xg + kt * KS;
        const __nv_bfloat16* esrc = eg + kt * KS;
        __nv_bfloat16* Ad = As + (size_t)s * BM * LDA;
        __nv_bfloat16* Bd = Bs + (size_t)s * BN * LDA;
        cp16(Ad + lr * LDA + ls * 8,         xsrc + (size_t)lr * DIM + ls * 8);
        cp16(Ad + (lr + 64) * LDA + ls * 8,  xsrc + (size_t)(lr + 64) * DIM + ls * 8);
        cp16(Bd + lr * LDA + ls * 8,         esrc + (size_t)lr * DIM + ls * 8);
        cp16(Bd + (lr + 64) * LDA + ls * 8,  esrc + (size_t)(lr + 64) * DIM + ls * 8);
    };

    issue(0, 0); CP_COMMIT();
    issue(1, 1); CP_COMMIT();

    int sc = 0, si = 2;
    #pragma unroll 1
    for (int kt = 0; kt < KT; kt++) {
        CP_WAIT1();
        __syncthreads();
        if (kt + NSTAGE - 1 < KT) issue(kt + NSTAGE - 1, si);
        CP_COMMIT();

        const __nv_bfloat16* Ab = As + (size_t)sc * BM * LDA;
        const __nv_bfloat16* Bb = Bs + (size_t)sc * BN * LDA;
        #pragma unroll
        for (int kk = 0; kk < 2; kk++) {
            unsigned a[4][4], b[4][2];
            #pragma unroll
            for (int mi = 0; mi < 4; mi++)
                ldsm_x4(a[mi][0], a[mi][1], a[mi][2], a[mi][3],
                        Ab + (warp_m * 64 + mi * 16 + (lane & 15)) * LDA
                           + kk * 16 + ((lane >> 4) << 3));
            #pragma unroll
            for (int nib = 0; nib < 2; nib++) {
                unsigned r0, r1, r2, r3;
                ldsm_x4(r0, r1, r2, r3,
                        Bb + (warp_n * 32 + nib * 16 + ((lane >> 4) << 3) + (lane & 7)) * LDA
                           + kk * 16 + (((lane >> 3) & 1) << 3));
                b[nib * 2][0] = r0; b[nib * 2][1] = r1;
                b[nib * 2 + 1][0] = r2; b[nib * 2 + 1][1] = r3;
            }
            #pragma unroll
            for (int mi = 0; mi < 4; mi++)
                #pragma unroll
                for (int ni = 0; ni < 4; ni++)
                    mma_bf16(acc[mi][ni], a[mi], b[ni]);
        }
        sc = (sc + 1 == NSTAGE) ? 0 : sc + 1;
        si = (si + 1 == NSTAGE) ? 0 : si + 1;
    }

    // epilogue: dv = -sqrt(max((x2+y2) + (-2*xy), 0)); approx per-row max
    int qr = lane >> 2, qc = 2 * (lane & 3);
    float x2v[4][2], rmax[4][2];
    #pragma unroll
    for (int mi = 0; mi < 4; mi++)
        #pragma unroll
        for (int h = 0; h < 2; h++) {
            x2v[mi][h] = g_x2[bm + warp_m * 64 + mi * 16 + h * 8 + qr];
            rmax[mi][h] = -1e30f;
        }

    #pragma unroll
    for (int ni = 0; ni < 4; ni++) {
        int n0 = bn + warp_n * 32 + ni * 8 + qc;
        float y0 = g_y2[n0], y1 = g_y2[n0 + 1];
        #pragma unroll
        for (int mi = 0; mi < 4; mi++)
            #pragma unroll
            for (int h = 0; h < 2; h++) {
                int rg = bm + warp_m * 64 + mi * 16 + h * 8 + qr;
                float s0 = acc[mi][ni][2 * h], s1 = acc[mi][ni][2 * h + 1];
                float d0 = -sqrtf(fmaxf(__fadd_rn(__fadd_rn(x2v[mi][h], y0), __fmul_rn(-2.0f, s0)), 0.0f));
                float d1 = -sqrtf(fmaxf(__fadd_rn(__fadd_rn(x2v[mi][h], y1), __fmul_rn(-2.0f, s1)), 0.0f));
                *reinterpret_cast<float2*>(&dist[(size_t)rg * NCODE + n0]) = make_float2(d0, d1);
                rmax[mi][h] = fmaxf(rmax[mi][h], fmaxf(d0, d1));
            }
    }
    #pragma unroll
    for (int mi = 0; mi < 4; mi++)
        #pragma unroll
        for (int h = 0; h < 2; h++) {
            float v = rmax[mi][h];
            v = fmaxf(v, __shfl_xor_sync(0xffffffffu, v, 1));
            v = fmaxf(v, __shfl_xor_sync(0xffffffffu, v, 2));
            if ((lane & 3) == 0)
                atomicMax(&g_rowmax[bm + warp_m * 64 + mi * 16 + h * 8 + qr], fkey(v));
        }
}

// one warp per row: candidates within MARGIN of approx max, re-evaluated with the
// EXACT validated chain (sequential ascending-k fmaf + exact epilogue roundings).
#define RWARPS 8
__global__ __launch_bounds__(256)
void rescue(const float* __restrict__ x, const float* __restrict__ e,
            const float* __restrict__ dist) {
    __shared__ int s_cnt[RWARPS];
    __shared__ int s_cand[RWARPS][MAXCAND];

    int w = threadIdx.x >> 5, lane = threadIdx.x & 31;
    int row = blockIdx.x * RWARPS + w;

    if (lane == 0) s_cnt[w] = 0;
    __syncwarp();

    float thr = fkey_inv(g_rowmax[row]) - MARGIN;
    const float4* dp = reinterpret_cast<const float4*>(dist + (size_t)row * NCODE);
    for (int j = lane; j < NCODE / 4; j += 32) {
        float4 v = dp[j];
        #pragma unroll
        for (int q = 0; q < 4; q++) {
            float dv = (q == 0) ? v.x : (q == 1) ? v.y : (q == 2) ? v.z : v.w;
            if (dv >= thr) {
                int slot = atomicAdd(&s_cnt[w], 1);
                if (slot < MAXCAND) s_cand[w][slot] = 4 * j + q;
            }
        }
    }
    __syncwarp();
    int cnt = s_cnt[w];
    if (cnt > MAXCAND) cnt = MAXCAND;

    unsigned long long key = 0ull;
    if (lane < cnt) {
        int c = s_cand[w][lane];
        const float* xr = x + (size_t)row * DIM;
        const float* er = e + (size_t)c * DIM;
        float s = 0.0f;
        #pragma unroll 8
        for (int k = 0; k < DIM; k++)          // strictly ascending-k fp32 FMA chain
            s = fmaf(xr[k], er[k], s);
        float xyv = __fmul_rn(-2.0f, s);
        float t   = __fadd_rn(g_x2[row], g_y2[c]);
        float dsq = __fadd_rn(t, xyv);
        float dv  = -sqrtf(fmaxf(dsq, 0.0f));
        key = ((unsigned long long)fkey(dv) << 32) | (unsigned int)(NCODE - 1 - c);
    }
    #pragma unroll
    for (int off = 16; off > 0; off >>= 1) {
        unsigned long long o = __shfl_xor_sync(0xffffffffu, key, off);
        key = (o > key) ? o : key;
    }
    if (lane == 0)
        g_bestidx[row] = (NCODE - 1) - (int)(unsigned int)(key & 0xFFFFFFFFull);
}

__global__ void finalize(const float* __restrict__ embed,
                         float* __restrict__ out_q,
                         float* __restrict__ out_ind) {
    int row = blockIdx.x;
    int c = g_bestidx[row];
    if (threadIdx.x == 0) out_ind[row] = (float)c;
    const float4* src = reinterpret_cast<const float4*>(embed + (size_t)c * DIM);
    float4* dst = reinterpret_cast<float4*>(out_q + (size_t)row * DIM);
    for (int j = threadIdx.x; j < DIM / 4; j += blockDim.x) dst[j] = src[j];
}

extern "C" void kernel_launch(void* const* d_in, const int* in_sizes, int n_in,
                              void* d_out, int out_size) {
    const float* x = (const float*)d_in[0];      // [32768, 512]
    const float* e = (const float*)d_in[1];      // [8192, 512]
    float* out = (float*)d_out;

    float* out_q    = out;                                   // [N, D]
    float* out_ind  = out + (size_t)NROWS * DIM;             // [N]
    float* out_dist = out + (size_t)NROWS * DIM + NROWS;     // [N, C]

    float *d_x2, *d_y2;
    __nv_bfloat16 *d_xb, *d_eb;
    cudaGetSymbolAddress((void**)&d_x2, g_x2);
    cudaGetSymbolAddress((void**)&d_y2, g_y2);
    cudaGetSymbolAddress((void**)&d_xb, g_xb);
    cudaGetSymbolAddress((void**)&d_eb, g_eb);

    cudaFuncSetAttribute(gemm_bf16, cudaFuncAttributeMaxDynamicSharedMemorySize, SMEM_BYTES);

    init_scratch<<<(NROWS + 255) / 256, 256>>>();
    convert_bf16<<<(NROWS * DIM / 4 + 255) / 256, 256>>>(x, d_xb, NROWS * DIM / 4);
    convert_bf16<<<(NCODE * DIM / 4 + 255) / 256, 256>>>(e, d_eb, NCODE * DIM / 4);
    row_norms_seq<<<NROWS / 128, 128>>>(x, d_x2, NROWS);
    row_norms_seq<<<NCODE / 128, 128>>>(e, d_y2, NCODE);

    dim3 grid(NCODE / BN, NROWS / BM);
    gemm_bf16<<<grid, 256, SMEM_BYTES>>>(out_dist);

    rescue<<<NROWS / RWARPS, 256>>>(x, e, out_dist);

    finalize<<<NROWS, 128>>>(e, out_q, out_ind);
}